// round 7
// baseline (speedup 1.0000x reference)
#include <cuda_runtime.h>
#include <cstdint>

// MultiScaleDeformableAttention — float4 gather + L1-prefetch software pipeline.
//
// value:              (8, 22223, 8, 32)  float32
// sampling_locations: (8, 900, 8, 4, 4, 2) float32
// attention_weights:  (8, 900, 8, 4, 4) float32
// out:                (8, 900, 256) float32
//
// 8 threads per (b,q,h) tuple; each thread owns 4 channels (float4).
// Rotating 3-stage buffer holds only OFFSETS + WEIGHTS (8 regs/stage).
// While consuming point p, we compute point p+2's offsets and issue
// prefetch.global.L1 for its 4 corner lines (each tuple-corner is exactly
// one 128B line). Consume loads then hit L1 (~39cyc) instead of
// L2/DRAM (234-577cyc) — latency hiding without fat data registers.

#define NQ 900
#define NH 8
#define ND 32
#define BS 8
#define NKEYS 22223
#define NTUP (BS * NQ * NH)        // 57600 tuples
#define TPT 8                      // threads per tuple (32 channels / 4)
#define VSTRIDE (NH * ND)          // 256 floats per key

__device__ __forceinline__ void point_setup(
    const float* __restrict__ locp, const float* __restrict__ awp,
    int pi, int H, int W, int S,
    int& o00, int& o10, int& o01, int& o11,
    float& w00, float& w10, float& w01, float& w11)
{
    const float2 lxy = __ldg((const float2*)locp + pi);
    const float  w   = __ldg(&awp[pi]);

    const float x = lxy.x * (float)W - 0.5f;
    const float y = lxy.y * (float)H - 0.5f;
    const float x0f = floorf(x);
    const float y0f = floorf(y);
    const int x0 = (int)x0f;
    const int y0 = (int)y0f;
    const int x1 = x0 + 1;
    const int y1 = y0 + 1;
    const float fx1 = x - x0f;
    const float fy1 = y - y0f;
    const float fx0 = 1.0f - fx1;
    const float fy0 = 1.0f - fy1;

    // zero the weight factor for OOB corners; fold aw into the y factors.
    const float mx0 = (x0 >= 0 && x0 < W) ? fx0 : 0.0f;
    const float mx1 = (x1 >= 0 && x1 < W) ? fx1 : 0.0f;
    const float my0 = (y0 >= 0 && y0 < H) ? fy0 * w : 0.0f;
    const float my1 = (y1 >= 0 && y1 < H) ? fy1 * w : 0.0f;

    const int cx0 = min(max(x0, 0), W - 1);
    const int cx1 = min(max(x1, 0), W - 1);
    const int cy0 = min(max(y0, 0), H - 1);
    const int cy1 = min(max(y1, 0), H - 1);

    const int r0 = S + cy0 * W;
    const int r1 = S + cy1 * W;

    o00 = (r0 + cx0) * VSTRIDE;
    o10 = (r0 + cx1) * VSTRIDE;
    o01 = (r1 + cx0) * VSTRIDE;
    o11 = (r1 + cx1) * VSTRIDE;

    w00 = mx0 * my0;
    w10 = mx1 * my0;
    w01 = mx0 * my1;
    w11 = mx1 * my1;
}

__device__ __forceinline__ void prefetch_corners(
    const float* __restrict__ vbase, int c4,
    int o00, int o10, int o01, int o11)
{
    // lanes with c4 < 4 each prefetch one corner line (corner = c4).
    // Each tuple-corner is a single 128B-aligned line (8 threads x 16B).
    const int ta = (c4 & 2) ? o01 : o00;
    const int tb = (c4 & 2) ? o11 : o10;
    const int off = (c4 & 1) ? tb : ta;
    if (c4 < 4) {
        const float* p = vbase + off;
        asm volatile("prefetch.global.L1 [%0];" :: "l"(p));
    }
}

__global__ __launch_bounds__(256)
void msda_kernel(const float* __restrict__ value,
                 const float* __restrict__ loc,
                 const float* __restrict__ aw,
                 float* __restrict__ out)
{
    const int gt = blockIdx.x * blockDim.x + threadIdx.x;
    const int t  = gt >> 3;        // tuple id
    const int c4 = gt & 7;         // channel-group (4 floats)

    // t = (b*NQ + q)*NH + h
    const int h  = t & 7;
    const int b  = (t >> 3) / NQ;

    const float* __restrict__ locp = loc + (size_t)t * 32;
    const float* __restrict__ awp  = aw  + (size_t)t * 16;

    const float* __restrict__ vbase =
        value + (size_t)b * (NKEYS * NH * ND) + h * ND + c4 * 4;

    const int LVL_H[4] = {100, 50, 25, 13};
    const int LVL_W[4] = {167, 84, 42, 21};
    const int LVL_S[4] = {0, 16700, 20900, 21950};

    // 3-stage rotating buffer: offsets + weights only (8 regs per stage)
    int   o00[3], o10[3], o01[3], o11[3];
    float w00[3], w10[3], w01[3], w11[3];

    // prologue: setup + prefetch points 0 and 1
    #pragma unroll
    for (int pi = 0; pi < 2; ++pi) {
        const int l = pi >> 2;
        point_setup(locp, awp, pi, LVL_H[l], LVL_W[l], LVL_S[l],
                    o00[pi], o10[pi], o01[pi], o11[pi],
                    w00[pi], w10[pi], w01[pi], w11[pi]);
        prefetch_corners(vbase, c4, o00[pi], o10[pi], o01[pi], o11[pi]);
    }

    float4 acc0 = make_float4(0.f, 0.f, 0.f, 0.f);
    float4 acc1 = make_float4(0.f, 0.f, 0.f, 0.f);

    #pragma unroll
    for (int pi = 0; pi < 16; ++pi) {
        const int cur = pi % 3;

        // setup + prefetch point pi+2 before consuming point pi
        if (pi < 14) {
            const int nxt = (pi + 2) % 3;
            const int pn  = pi + 2;
            const int l   = pn >> 2;
            point_setup(locp, awp, pn, LVL_H[l], LVL_W[l], LVL_S[l],
                        o00[nxt], o10[nxt], o01[nxt], o11[nxt],
                        w00[nxt], w10[nxt], w01[nxt], w11[nxt]);
            prefetch_corners(vbase, c4, o00[nxt], o10[nxt], o01[nxt], o11[nxt]);
        }

        // consume point pi (loads should hit L1 thanks to the prefetch)
        const float4 p00 = __ldg((const float4*)(vbase + o00[cur]));
        const float4 p10 = __ldg((const float4*)(vbase + o10[cur]));
        const float4 p01 = __ldg((const float4*)(vbase + o01[cur]));
        const float4 p11 = __ldg((const float4*)(vbase + o11[cur]));

        const float a = w00[cur], bw = w10[cur], c = w01[cur], d = w11[cur];
        float4& acc = (pi & 1) ? acc1 : acc0;

        acc.x = fmaf(a, p00.x, acc.x);
        acc.y = fmaf(a, p00.y, acc.y);
        acc.z = fmaf(a, p00.z, acc.z);
        acc.w = fmaf(a, p00.w, acc.w);

        acc.x = fmaf(bw, p10.x, acc.x);
        acc.y = fmaf(bw, p10.y, acc.y);
        acc.z = fmaf(bw, p10.z, acc.z);
        acc.w = fmaf(bw, p10.w, acc.w);

        acc.x = fmaf(c, p01.x, acc.x);
        acc.y = fmaf(c, p01.y, acc.y);
        acc.z = fmaf(c, p01.z, acc.z);
        acc.w = fmaf(c, p01.w, acc.w);

        acc.x = fmaf(d, p11.x, acc.x);
        acc.y = fmaf(d, p11.y, acc.y);
        acc.z = fmaf(d, p11.z, acc.z);
        acc.w = fmaf(d, p11.w, acc.w);
    }

    float4 r;
    r.x = acc0.x + acc1.x;
    r.y = acc0.y + acc1.y;
    r.z = acc0.z + acc1.z;
    r.w = acc0.w + acc1.w;

    // out: tuple-major float4: out[t*8 + c4]
    ((float4*)out)[(size_t)t * 8 + c4] = r;
}

extern "C" void kernel_launch(void* const* d_in, const int* in_sizes, int n_in,
                              void* d_out, int out_size)
{
    const float* value = (const float*)d_in[0];
    const float* loc   = (const float*)d_in[1];
    const float* aw    = (const float*)d_in[2];
    float* out = (float*)d_out;

    const int total_threads = NTUP * TPT;          // 460800
    const int threads = 256;
    const int blocks = total_threads / threads;    // 1800 (exact)
    msda_kernel<<<blocks, threads>>>(value, loc, aw, out);
}

// round 9
// speedup vs baseline: 1.0037x; 1.0037x over previous
#include <cuda_runtime.h>
#include <cstdint>

// MultiScaleDeformableAttention — TLP gather: thread per (tuple, point, c4).
//
// value:              (8, 22223, 8, 32)  float32
// sampling_locations: (8, 900, 8, 4, 4, 2) float32
// attention_weights:  (8, 900, 8, 4, 4) float32
// out:                (8, 900, 256) float32
//
// 128 threads per (b,q,h) tuple: 16 points x 8 channel-groups (float4).
// Each thread: one bilinear setup, 4 independent LDG.128 corner loads,
// 16 FMAs -> per-point partial. Reduce the 16 points via 2 shfl.xor steps
// (within-warp: 4 points/warp) + a tiny smem combine across the 4 warps.
// Latency is hidden by warp count (4 loads x 64 warps/SM in flight),
// not by register-resident pipelines.

#define NQ 900
#define NH 8
#define ND 32
#define BS 8
#define NKEYS 22223
#define NTUP (BS * NQ * NH)        // 57600 tuples
#define VSTRIDE (NH * ND)          // 256 floats per key

__global__ __launch_bounds__(256)
void msda_kernel(const float* __restrict__ value,
                 const float* __restrict__ loc,
                 const float* __restrict__ aw,
                 float* __restrict__ out)
{
    __shared__ float4 red[2][4][8];   // [tuple_in_block][level_warp][c4]

    const int tib   = threadIdx.x >> 7;        // tuple within block (0..1)
    const int gtid  = threadIdx.x & 127;       // thread within tuple group
    const int point = gtid >> 3;               // 0..15
    const int c4    = gtid & 7;                // channel group (4 floats)
    const int t     = blockIdx.x * 2 + tib;    // tuple id

    // t = (b*NQ + q)*NH + h
    const int h = t & 7;
    const int b = (t >> 3) / NQ;

    // per-(tuple,point) location + weight (broadcast across the 8 c4 lanes)
    const float2 lxy = __ldg((const float2*)(loc + (size_t)t * 32) + point);
    const float  w   = __ldg(aw + (size_t)t * 16 + point);

    // level = point >> 2 — warp-uniform (warp covers 4 points of one level)
    const int l = point >> 2;
    const int H = (l == 0) ? 100 : (l == 1) ? 50 : (l == 2) ? 25 : 13;
    const int W = (l == 0) ? 167 : (l == 1) ? 84 : (l == 2) ? 42 : 21;
    const int S = (l == 0) ? 0 : (l == 1) ? 16700 : (l == 2) ? 20900 : 21950;

    // bilinear setup
    const float x = lxy.x * (float)W - 0.5f;
    const float y = lxy.y * (float)H - 0.5f;
    const float x0f = floorf(x);
    const float y0f = floorf(y);
    const int x0 = (int)x0f;
    const int y0 = (int)y0f;
    const int x1 = x0 + 1;
    const int y1 = y0 + 1;
    const float fx1 = x - x0f;
    const float fy1 = y - y0f;
    const float fx0 = 1.0f - fx1;
    const float fy0 = 1.0f - fy1;

    // zero the weight factor for OOB corners; fold aw into the y factors
    const float mx0 = (x0 >= 0 && x0 < W) ? fx0 : 0.0f;
    const float mx1 = (x1 >= 0 && x1 < W) ? fx1 : 0.0f;
    const float my0 = (y0 >= 0 && y0 < H) ? fy0 * w : 0.0f;
    const float my1 = (y1 >= 0 && y1 < H) ? fy1 * w : 0.0f;

    const int cx0 = min(max(x0, 0), W - 1);
    const int cx1 = min(max(x1, 0), W - 1);
    const int cy0 = min(max(y0, 0), H - 1);
    const int cy1 = min(max(y1, 0), H - 1);

    const int r0 = S + cy0 * W;
    const int r1 = S + cy1 * W;

    const float* __restrict__ vbase =
        value + (size_t)b * (NKEYS * NH * ND) + h * ND + c4 * 4;

    // 4 independent 16B gathers (corner lines)
    const float4 p00 = __ldg((const float4*)(vbase + (r0 + cx0) * VSTRIDE));
    const float4 p10 = __ldg((const float4*)(vbase + (r0 + cx1) * VSTRIDE));
    const float4 p01 = __ldg((const float4*)(vbase + (r1 + cx0) * VSTRIDE));
    const float4 p11 = __ldg((const float4*)(vbase + (r1 + cx1) * VSTRIDE));

    const float w00 = mx0 * my0;
    const float w10 = mx1 * my0;
    const float w01 = mx0 * my1;
    const float w11 = mx1 * my1;

    float4 s;
    s.x = fmaf(w00, p00.x, fmaf(w10, p10.x, fmaf(w01, p01.x, w11 * p11.x)));
    s.y = fmaf(w00, p00.y, fmaf(w10, p10.y, fmaf(w01, p01.y, w11 * p11.y)));
    s.z = fmaf(w00, p00.z, fmaf(w10, p10.z, fmaf(w01, p01.z, w11 * p11.z)));
    s.w = fmaf(w00, p00.w, fmaf(w10, p10.w, fmaf(w01, p01.w, w11 * p11.w)));

    // reduce over the warp's 4 points (lane = c4 + 8*(point%4))
    const unsigned FULL = 0xFFFFFFFFu;
    s.x += __shfl_xor_sync(FULL, s.x, 8);
    s.y += __shfl_xor_sync(FULL, s.y, 8);
    s.z += __shfl_xor_sync(FULL, s.z, 8);
    s.w += __shfl_xor_sync(FULL, s.w, 8);
    s.x += __shfl_xor_sync(FULL, s.x, 16);
    s.y += __shfl_xor_sync(FULL, s.y, 16);
    s.z += __shfl_xor_sync(FULL, s.z, 16);
    s.w += __shfl_xor_sync(FULL, s.w, 16);

    // lanes 0..7 hold the warp's point-sum for their c4
    if ((threadIdx.x & 31) < 8)
        red[tib][gtid >> 5][c4] = s;
    __syncthreads();

    // 8 threads per tuple combine the 4 level-warps and store
    if (gtid < 8) {
        const float4 a0 = red[tib][0][c4];
        const float4 a1 = red[tib][1][c4];
        const float4 a2 = red[tib][2][c4];
        const float4 a3 = red[tib][3][c4];
        float4 r;
        r.x = (a0.x + a1.x) + (a2.x + a3.x);
        r.y = (a0.y + a1.y) + (a2.y + a3.y);
        r.z = (a0.z + a1.z) + (a2.z + a3.z);
        r.w = (a0.w + a1.w) + (a2.w + a3.w);
        ((float4*)out)[(size_t)t * 8 + c4] = r;
    }
}

extern "C" void kernel_launch(void* const* d_in, const int* in_sizes, int n_in,
                              void* d_out, int out_size)
{
    const float* value = (const float*)d_in[0];
    const float* loc   = (const float*)d_in[1];
    const float* aw    = (const float*)d_in[2];
    float* out = (float*)d_out;

    const int threads = 256;                   // 2 tuples per block
    const int blocks  = NTUP / 2;              // 28800 (exact)
    msda_kernel<<<blocks, threads>>>(value, loc, aw, out);
}

// round 10
// speedup vs baseline: 1.3899x; 1.3847x over previous
#include <cuda_runtime.h>
#include <cstdint>

// MultiScaleDeformableAttention — float4 gather + depth-2 software pipeline,
// with registers GRANTED via __launch_bounds__(256, 3) (85 regs/thread) so
// the 3-stage register-resident pipeline survives ptxas scheduling.
//
// value:              (8, 22223, 8, 32)  float32
// sampling_locations: (8, 900, 8, 4, 4, 2) float32
// attention_weights:  (8, 900, 8, 4, 4) float32
// out:                (8, 900, 256) float32
//
// 8 threads per (b,q,h) tuple; each thread owns 4 channels (float4).
// Loads for point p+2 are issued while FMAs consume point p ->
// ~12 independent LDG.128 in flight per warp.

#define NQ 900
#define NH 8
#define ND 32
#define BS 8
#define NKEYS 22223
#define NTUP (BS * NQ * NH)        // 57600 tuples
#define TPT 8                      // threads per tuple (32 channels / 4)
#define VSTRIDE (NH * ND)          // 256 floats per key

__device__ __forceinline__ void point_setup(
    float lx, float ly, float w,
    int H, int W, int S,
    int& o00, int& o10, int& o01, int& o11,
    float& w00, float& w10, float& w01, float& w11)
{
    const float x = lx * (float)W - 0.5f;
    const float y = ly * (float)H - 0.5f;
    const float x0f = floorf(x);
    const float y0f = floorf(y);
    const int x0 = (int)x0f;
    const int y0 = (int)y0f;
    const int x1 = x0 + 1;
    const int y1 = y0 + 1;
    const float fx1 = x - x0f;
    const float fy1 = y - y0f;
    const float fx0 = 1.0f - fx1;
    const float fy0 = 1.0f - fy1;

    // zero weight factor when the corner is out of range; fold aw in.
    const float mx0 = (x0 >= 0 && x0 < W) ? fx0 : 0.0f;
    const float mx1 = (x1 >= 0 && x1 < W) ? fx1 : 0.0f;
    const float my0 = (y0 >= 0 && y0 < H) ? fy0 * w : 0.0f;
    const float my1 = (y1 >= 0 && y1 < H) ? fy1 * w : 0.0f;

    const int cx0 = min(max(x0, 0), W - 1);
    const int cx1 = min(max(x1, 0), W - 1);
    const int cy0 = min(max(y0, 0), H - 1);
    const int cy1 = min(max(y1, 0), H - 1);

    const int r0 = S + cy0 * W;
    const int r1 = S + cy1 * W;

    o00 = (r0 + cx0) * VSTRIDE;
    o10 = (r0 + cx1) * VSTRIDE;
    o01 = (r1 + cx0) * VSTRIDE;
    o11 = (r1 + cx1) * VSTRIDE;

    w00 = mx0 * my0;
    w10 = mx1 * my0;
    w01 = mx0 * my1;
    w11 = mx1 * my1;
}

__global__ __launch_bounds__(256, 3)   // cap 3 CTAs/SM -> 85 regs/thread
void msda_kernel(const float* __restrict__ value,
                 const float* __restrict__ loc,
                 const float* __restrict__ aw,
                 float* __restrict__ out)
{
    const int gt = blockIdx.x * blockDim.x + threadIdx.x;
    const int t  = gt >> 3;        // tuple id
    const int c4 = gt & 7;         // channel-group (4 floats)

    // t = (b*NQ + q)*NH + h
    const int h  = t & 7;
    const int b  = (t >> 3) / NQ;

    // batched per-tuple parameter loads:
    //   loc: 32 floats = 8 float4 (2 points per float4)
    //   aw : 16 floats = 4 float4 (4 points per float4)
    const float4* __restrict__ locp4 = (const float4*)(loc + (size_t)t * 32);
    const float4* __restrict__ awp4  = (const float4*)(aw  + (size_t)t * 16);

    const float* __restrict__ vbase =
        value + (size_t)b * (NKEYS * NH * ND) + h * ND + c4 * 4;

    const int LVL_H[4] = {100, 50, 25, 13};
    const int LVL_W[4] = {167, 84, 42, 21};
    const int LVL_S[4] = {0, 16700, 20900, 21950};

    // 3-stage rotating pipeline state (fully unrolled -> registers)
    float4 v00[3], v10[3], v01[3], v11[3];
    float  w00[3], w10[3], w01[3], w11[3];

    // helper lambda: setup + issue loads for point pi into slot s
    auto issue = [&](int pi, int s) {
        const int l = pi >> 2;
        const float4 lpair = __ldg(locp4 + (pi >> 1));     // 2 points' (x,y)
        const float  lx = (pi & 1) ? lpair.z : lpair.x;
        const float  ly = (pi & 1) ? lpair.w : lpair.y;
        const float4 w4 = __ldg(awp4 + l);                 // 4 points' aw
        const float  w  = (pi & 2) ? ((pi & 1) ? w4.w : w4.z)
                                   : ((pi & 1) ? w4.y : w4.x);
        int o00, o10, o01, o11;
        point_setup(lx, ly, w, LVL_H[l], LVL_W[l], LVL_S[l],
                    o00, o10, o01, o11,
                    w00[s], w10[s], w01[s], w11[s]);
        v00[s] = __ldg((const float4*)(vbase + o00));
        v10[s] = __ldg((const float4*)(vbase + o10));
        v01[s] = __ldg((const float4*)(vbase + o01));
        v11[s] = __ldg((const float4*)(vbase + o11));
    };

    // prologue: fill slots for points 0 and 1
    issue(0, 0);
    issue(1, 1);

    float4 acc0 = make_float4(0.f, 0.f, 0.f, 0.f);
    float4 acc1 = make_float4(0.f, 0.f, 0.f, 0.f);

    #pragma unroll
    for (int pi = 0; pi < 16; ++pi) {
        const int cur = pi % 3;

        // issue loads for point pi+2 before consuming point pi
        if (pi < 14)
            issue(pi + 2, (pi + 2) % 3);

        const float a = w00[cur], bw = w10[cur], c = w01[cur], d = w11[cur];
        const float4 p00 = v00[cur], p10 = v10[cur], p01 = v01[cur], p11 = v11[cur];
        float4& acc = (pi & 1) ? acc1 : acc0;

        acc.x = fmaf(a, p00.x, acc.x);
        acc.y = fmaf(a, p00.y, acc.y);
        acc.z = fmaf(a, p00.z, acc.z);
        acc.w = fmaf(a, p00.w, acc.w);

        acc.x = fmaf(bw, p10.x, acc.x);
        acc.y = fmaf(bw, p10.y, acc.y);
        acc.z = fmaf(bw, p10.z, acc.z);
        acc.w = fmaf(bw, p10.w, acc.w);

        acc.x = fmaf(c, p01.x, acc.x);
        acc.y = fmaf(c, p01.y, acc.y);
        acc.z = fmaf(c, p01.z, acc.z);
        acc.w = fmaf(c, p01.w, acc.w);

        acc.x = fmaf(d, p11.x, acc.x);
        acc.y = fmaf(d, p11.y, acc.y);
        acc.z = fmaf(d, p11.z, acc.z);
        acc.w = fmaf(d, p11.w, acc.w);
    }

    float4 r;
    r.x = acc0.x + acc1.x;
    r.y = acc0.y + acc1.y;
    r.z = acc0.z + acc1.z;
    r.w = acc0.w + acc1.w;

    // out: tuple-major float4: out[t*8 + c4]
    ((float4*)out)[(size_t)t * 8 + c4] = r;
}

extern "C" void kernel_launch(void* const* d_in, const int* in_sizes, int n_in,
                              void* d_out, int out_size)
{
    const float* value = (const float*)d_in[0];
    const float* loc   = (const float*)d_in[1];
    const float* aw    = (const float*)d_in[2];
    float* out = (float*)d_out;

    const int total_threads = NTUP * TPT;          // 460800
    const int threads = 256;
    const int blocks = total_threads / threads;    // 1800 (exact)
    msda_kernel<<<blocks, threads>>>(value, loc, aw, out);
}